// round 3
// baseline (speedup 1.0000x reference)
#include <cuda_runtime.h>
#include <math.h>

#define NB 64
#define SS 512
#define HH 768
#define CC 50
#define MM 2000
#define TT (NB*SS)   // 32768

// ---------------- scratch (device globals; no allocations allowed) ----------
__device__ float g_nts[TT];
__device__ float g_mts[TT];
__device__ float g_uts[TT];
__device__ float g_names_emb[(size_t)CC*NB*HH];  // 9.8 MB
__device__ float g_nscore[CC*NB];
__device__ float g_name_e[CC*HH];
__device__ float g_memb[(size_t)MM*HH];          // 6 MB
__device__ float g_mscore[MM];
__device__ float g_mention_e[CC*HH];
__device__ int   g_mcount[CC];
__device__ float g_utt_e[CC*HH];
__device__ int   g_has_utt[CC];

// ---------------- reductions (blockDim == 256) ------------------------------
__device__ __forceinline__ float warpSum(float v){
    #pragma unroll
    for(int o=16;o;o>>=1) v += __shfl_xor_sync(0xffffffffu, v, o);
    return v;
}
__device__ __forceinline__ float warpMax(float v){
    #pragma unroll
    for(int o=16;o;o>>=1) v = fmaxf(v, __shfl_xor_sync(0xffffffffu, v, o));
    return v;
}
__device__ __forceinline__ float blockSum(float v, float* buf){
    int lane = threadIdx.x & 31, wid = threadIdx.x >> 5;
    v = warpSum(v);
    if(lane == 0) buf[wid] = v;
    __syncthreads();
    if(wid == 0){
        float r = (lane < 8) ? buf[lane] : 0.f;
        r = warpSum(r);
        if(lane == 0) buf[0] = r;
    }
    __syncthreads();
    float r = buf[0];
    __syncthreads();
    return r;
}
__device__ __forceinline__ float blockMax(float v, float* buf){
    int lane = threadIdx.x & 31, wid = threadIdx.x >> 5;
    v = warpMax(v);
    if(lane == 0) buf[wid] = v;
    __syncthreads();
    if(wid == 0){
        float r = (lane < 8) ? buf[lane] : -INFINITY;
        r = warpMax(r);
        if(lane == 0) buf[0] = r;
    }
    __syncthreads();
    float r = buf[0];
    __syncthreads();
    return r;
}

// ---------------- k1: per-token scalars nts/mts/uts --------------------------
// warp-per-token; grid = TT/8, 256 threads
__global__ void k_token(const float* __restrict__ se,
                        const float* __restrict__ wn, const float* __restrict__ bn,
                        const float* __restrict__ wm, const float* __restrict__ bm,
                        const float* __restrict__ wu, const float* __restrict__ bu){
    __shared__ float sw[3*HH];
    for(int i=threadIdx.x;i<HH;i+=256){
        sw[i]=wn[i]; sw[HH+i]=wm[i]; sw[2*HH+i]=wu[i];
    }
    __syncthreads();
    int warp = threadIdx.x >> 5, lane = threadIdx.x & 31;
    int t = blockIdx.x*8 + warp;
    const float* row = se + (size_t)t*HH;
    float a=0.f, b=0.f, c=0.f;
    #pragma unroll 4
    for(int i=lane;i<HH;i+=32){
        float x = row[i];
        a = fmaf(x, sw[i],      a);
        b = fmaf(x, sw[HH+i],   b);
        c = fmaf(x, sw[2*HH+i], c);
    }
    a = warpSum(a); b = warpSum(b); c = warpSum(c);
    if(lane == 0){
        g_nts[t] = a + bn[0];
        g_mts[t] = b + bm[0];
        g_uts[t] = c + bu[0];
    }
}

// ---------------- k2: names per (c,b) attention + score ----------------------
// one CTA per (c,b): grid = CC*NB
__global__ void k_names(const float* __restrict__ se,
                        const float* __restrict__ nmask,
                        const float* __restrict__ w_name,
                        const float* __restrict__ b_name){
    __shared__ int   s_idx[SS];
    __shared__ float s_w[SS];
    __shared__ float s_buf[32];
    __shared__ int   s_cnt;
    int c = blockIdx.x / NB, b = blockIdx.x % NB, tid = threadIdx.x;
    if(tid==0) s_cnt = 0;
    __syncthreads();
    const float* mrow = nmask + c*SS;
    const float* ntsr = g_nts + b*SS;
    float lm = -INFINITY;
    for(int s=tid;s<SS;s+=256){
        if(mrow[s]==0.0f){
            int p = atomicAdd(&s_cnt,1);
            if(p < SS) s_idx[p] = s;
            lm = fmaxf(lm, ntsr[s]);
        }
    }
    float mx = blockMax(lm, s_buf);
    int cnt = min(s_cnt, SS);
    float ls = 0.f;
    for(int i=tid;i<cnt;i+=256){
        float e = __expf(ntsr[s_idx[i]] - mx);
        s_w[i] = e; ls += e;
    }
    float den = blockSum(ls, s_buf);
    float inv = 1.0f/den;
    const float* base = se + (size_t)b*SS*HH;
    float a0=0.f,a1=0.f,a2=0.f;
    int i=0;
    for(; i+4<=cnt; i+=4){
        float w0=s_w[i], w1=s_w[i+1], w2=s_w[i+2], w3=s_w[i+3];
        const float* r0 = base + s_idx[i]*HH;
        const float* r1 = base + s_idx[i+1]*HH;
        const float* r2 = base + s_idx[i+2]*HH;
        const float* r3 = base + s_idx[i+3]*HH;
        a0 = fmaf(w0,r0[tid],    fmaf(w1,r1[tid],    fmaf(w2,r2[tid],    fmaf(w3,r3[tid],    a0))));
        a1 = fmaf(w0,r0[tid+256],fmaf(w1,r1[tid+256],fmaf(w2,r2[tid+256],fmaf(w3,r3[tid+256],a1))));
        a2 = fmaf(w0,r0[tid+512],fmaf(w1,r1[tid+512],fmaf(w2,r2[tid+512],fmaf(w3,r3[tid+512],a2))));
    }
    for(; i<cnt; i++){
        float w = s_w[i];
        const float* r = base + s_idx[i]*HH;
        a0 = fmaf(w, r[tid],     a0);
        a1 = fmaf(w, r[tid+256], a1);
        a2 = fmaf(w, r[tid+512], a2);
    }
    a0*=inv; a1*=inv; a2*=inv;
    size_t off = ((size_t)c*NB + b)*HH;
    g_names_emb[off+tid]     = a0;
    g_names_emb[off+tid+256] = a1;
    g_names_emb[off+tid+512] = a2;
    float part = a0*w_name[tid] + a1*w_name[tid+256] + a2*w_name[tid+512];
    float sc = blockSum(part, s_buf);
    if(tid==0) g_nscore[c*NB + b] = sc + b_name[0];
}

// ---------------- k3: softmax over blocks -> name_e --------------------------
__global__ void k_name_e(){
    __shared__ float s_p[NB];
    __shared__ float s_buf[32];
    int c = blockIdx.x, tid = threadIdx.x;
    float v = (tid < NB) ? g_nscore[c*NB + tid] : -INFINITY;
    float mx = blockMax(v, s_buf);
    float e = (tid < NB) ? __expf(v - mx) : 0.f;
    float den = blockSum(e, s_buf);
    if(tid < NB) s_p[tid] = e/den;
    __syncthreads();
    float a0=0.f,a1=0.f,a2=0.f;
    #pragma unroll 4
    for(int b=0;b<NB;b++){
        float p = s_p[b];
        const float* r = g_names_emb + ((size_t)c*NB + b)*HH;
        a0 = fmaf(p, r[tid],     a0);
        a1 = fmaf(p, r[tid+256], a1);
        a2 = fmaf(p, r[tid+512], a2);
    }
    g_name_e[c*HH+tid]     = a0;
    g_name_e[c*HH+tid+256] = a1;
    g_name_e[c*HH+tid+512] = a2;
}

// ---------------- k4: mentions — sparse masked attention ---------------------
#define MCAP 2048
__global__ void k_mentions(const float* __restrict__ se,
                           const float* __restrict__ mmask,
                           const float* __restrict__ w_men,
                           const float* __restrict__ b_men){
    __shared__ int   s_idx[MCAP];
    __shared__ float s_w[MCAP];
    __shared__ float s_buf[32];
    __shared__ int   s_cnt;
    int m = blockIdx.x, tid = threadIdx.x;
    if(tid==0) s_cnt = 0;
    __syncthreads();
    const float4* row4 = (const float4*)(mmask + (size_t)m*TT);
    for(int i=tid;i<TT/4;i+=256){
        float4 v = __ldcs(row4 + i);     // streaming: don't evict se from L2
        int t = i*4;
        if(v.x==0.f){ int p=atomicAdd(&s_cnt,1); if(p<MCAP) s_idx[p]=t;   }
        if(v.y==0.f){ int p=atomicAdd(&s_cnt,1); if(p<MCAP) s_idx[p]=t+1; }
        if(v.z==0.f){ int p=atomicAdd(&s_cnt,1); if(p<MCAP) s_idx[p]=t+2; }
        if(v.w==0.f){ int p=atomicAdd(&s_cnt,1); if(p<MCAP) s_idx[p]=t+3; }
    }
    __syncthreads();
    int cnt = min(s_cnt, MCAP);
    float lm = -INFINITY;
    for(int i=tid;i<cnt;i+=256) lm = fmaxf(lm, g_mts[s_idx[i]]);
    float mx = blockMax(lm, s_buf);
    float ls = 0.f;
    for(int i=tid;i<cnt;i+=256){
        float e = __expf(g_mts[s_idx[i]] - mx);
        s_w[i] = e; ls += e;
    }
    float den = blockSum(ls, s_buf);
    float inv = 1.f/den;
    float a0=0.f,a1=0.f,a2=0.f;
    int i=0;
    for(; i+4<=cnt; i+=4){
        float w0=s_w[i], w1=s_w[i+1], w2=s_w[i+2], w3=s_w[i+3];
        const float* r0 = se + (size_t)s_idx[i]*HH;
        const float* r1 = se + (size_t)s_idx[i+1]*HH;
        const float* r2 = se + (size_t)s_idx[i+2]*HH;
        const float* r3 = se + (size_t)s_idx[i+3]*HH;
        a0 = fmaf(w0,__ldg(r0+tid),    fmaf(w1,__ldg(r1+tid),    fmaf(w2,__ldg(r2+tid),    fmaf(w3,__ldg(r3+tid),    a0))));
        a1 = fmaf(w0,__ldg(r0+tid+256),fmaf(w1,__ldg(r1+tid+256),fmaf(w2,__ldg(r2+tid+256),fmaf(w3,__ldg(r3+tid+256),a1))));
        a2 = fmaf(w0,__ldg(r0+tid+512),fmaf(w1,__ldg(r1+tid+512),fmaf(w2,__ldg(r2+tid+512),fmaf(w3,__ldg(r3+tid+512),a2))));
    }
    for(; i<cnt; i++){
        float w = s_w[i];
        const float* r = se + (size_t)s_idx[i]*HH;
        a0 = fmaf(w, __ldg(r+tid),     a0);
        a1 = fmaf(w, __ldg(r+tid+256), a1);
        a2 = fmaf(w, __ldg(r+tid+512), a2);
    }
    a0*=inv; a1*=inv; a2*=inv;
    size_t off = (size_t)m*HH;
    g_memb[off+tid]     = a0;
    g_memb[off+tid+256] = a1;
    g_memb[off+tid+512] = a2;
    float part = a0*w_men[tid] + a1*w_men[tid+256] + a2*w_men[tid+512];
    float sc = blockSum(part, s_buf);
    if(tid==0) g_mscore[m] = sc + b_men[0];
}

// ---------------- k5: segment softmax over mentions -> mention_e -------------
#define SCAP 512
__global__ void k_mention_e(const int* __restrict__ ids){
    __shared__ int   s_idx[SCAP];
    __shared__ float s_w[SCAP];
    __shared__ float s_buf[32];
    __shared__ int   s_cnt;
    int c = blockIdx.x, tid = threadIdx.x;
    if(tid==0) s_cnt = 0;
    __syncthreads();
    for(int m=tid;m<MM;m+=256)
        if(ids[m]==c){ int p=atomicAdd(&s_cnt,1); if(p<SCAP) s_idx[p]=m; }
    __syncthreads();
    int cnt = min(s_cnt, SCAP);
    if(tid==0) g_mcount[c] = cnt;
    float lm = -INFINITY;
    for(int i=tid;i<cnt;i+=256) lm = fmaxf(lm, g_mscore[s_idx[i]]);
    float mx = blockMax(lm, s_buf);
    float ls = 0.f;
    for(int i=tid;i<cnt;i+=256){
        float e = __expf(g_mscore[s_idx[i]] - mx);
        s_w[i] = e; ls += e;
    }
    float den = blockSum(ls, s_buf);
    float inv = cnt ? 1.f/den : 0.f;
    float a0=0.f,a1=0.f,a2=0.f;
    int i=0;
    for(; i+4<=cnt; i+=4){
        float w0=s_w[i]*inv, w1=s_w[i+1]*inv, w2=s_w[i+2]*inv, w3=s_w[i+3]*inv;
        const float* r0 = g_memb + (size_t)s_idx[i]*HH;
        const float* r1 = g_memb + (size_t)s_idx[i+1]*HH;
        const float* r2 = g_memb + (size_t)s_idx[i+2]*HH;
        const float* r3 = g_memb + (size_t)s_idx[i+3]*HH;
        a0 = fmaf(w0,r0[tid],    fmaf(w1,r1[tid],    fmaf(w2,r2[tid],    fmaf(w3,r3[tid],    a0))));
        a1 = fmaf(w0,r0[tid+256],fmaf(w1,r1[tid+256],fmaf(w2,r2[tid+256],fmaf(w3,r3[tid+256],a1))));
        a2 = fmaf(w0,r0[tid+512],fmaf(w1,r1[tid+512],fmaf(w2,r2[tid+512],fmaf(w3,r3[tid+512],a2))));
    }
    for(; i<cnt; i++){
        float w = s_w[i]*inv;
        const float* r = g_memb + (size_t)s_idx[i]*HH;
        a0 = fmaf(w, r[tid],     a0);
        a1 = fmaf(w, r[tid+256], a1);
        a2 = fmaf(w, r[tid+512], a2);
    }
    g_mention_e[c*HH+tid]     = a0;
    g_mention_e[c*HH+tid+256] = a1;
    g_mention_e[c*HH+tid+512] = a2;
}

// ---------------- k6: utterances — sparse masked attention -------------------
#define UCAP 2048
__global__ void k_utts(const float* __restrict__ se,
                       const float* __restrict__ umask){
    __shared__ int   s_idx[UCAP];
    __shared__ float s_w[UCAP];
    __shared__ float s_buf[32];
    __shared__ int   s_cnt;
    int c = blockIdx.x, tid = threadIdx.x;
    if(tid==0) s_cnt = 0;
    __syncthreads();
    const float4* row4 = (const float4*)(umask + (size_t)c*TT);
    for(int i=tid;i<TT/4;i+=256){
        float4 v = __ldcs(row4 + i);
        int t = i*4;
        if(v.x==0.f){ int p=atomicAdd(&s_cnt,1); if(p<UCAP) s_idx[p]=t;   }
        if(v.y==0.f){ int p=atomicAdd(&s_cnt,1); if(p<UCAP) s_idx[p]=t+1; }
        if(v.z==0.f){ int p=atomicAdd(&s_cnt,1); if(p<UCAP) s_idx[p]=t+2; }
        if(v.w==0.f){ int p=atomicAdd(&s_cnt,1); if(p<UCAP) s_idx[p]=t+3; }
    }
    __syncthreads();
    int cnt = min(s_cnt, UCAP);
    if(tid==0) g_has_utt[c] = (cnt > 0) ? 1 : 0;
    float lm = -INFINITY;
    for(int i=tid;i<cnt;i+=256) lm = fmaxf(lm, g_uts[s_idx[i]]);
    float mx = blockMax(lm, s_buf);
    float ls = 0.f;
    for(int i=tid;i<cnt;i+=256){
        float e = __expf(g_uts[s_idx[i]] - mx);
        s_w[i] = e; ls += e;
    }
    float den = blockSum(ls, s_buf);
    float inv = cnt ? 1.f/den : 0.f;   // nan_to_num path: empty -> zeros
    float a0=0.f,a1=0.f,a2=0.f;
    int i=0;
    for(; i+4<=cnt; i+=4){
        float w0=s_w[i]*inv, w1=s_w[i+1]*inv, w2=s_w[i+2]*inv, w3=s_w[i+3]*inv;
        const float* r0 = se + (size_t)s_idx[i]*HH;
        const float* r1 = se + (size_t)s_idx[i+1]*HH;
        const float* r2 = se + (size_t)s_idx[i+2]*HH;
        const float* r3 = se + (size_t)s_idx[i+3]*HH;
        a0 = fmaf(w0,__ldg(r0+tid),    fmaf(w1,__ldg(r1+tid),    fmaf(w2,__ldg(r2+tid),    fmaf(w3,__ldg(r3+tid),    a0))));
        a1 = fmaf(w0,__ldg(r0+tid+256),fmaf(w1,__ldg(r1+tid+256),fmaf(w2,__ldg(r2+tid+256),fmaf(w3,__ldg(r3+tid+256),a1))));
        a2 = fmaf(w0,__ldg(r0+tid+512),fmaf(w1,__ldg(r1+tid+512),fmaf(w2,__ldg(r2+tid+512),fmaf(w3,__ldg(r3+tid+512),a2))));
    }
    for(; i<cnt; i++){
        float w = s_w[i]*inv;
        const float* r = se + (size_t)s_idx[i]*HH;
        a0 = fmaf(w, __ldg(r+tid),     a0);
        a1 = fmaf(w, __ldg(r+tid+256), a1);
        a2 = fmaf(w, __ldg(r+tid+512), a2);
    }
    g_utt_e[c*HH+tid]     = a0;
    g_utt_e[c*HH+tid+256] = a1;
    g_utt_e[c*HH+tid+512] = a2;
}

// ---------------- k7: combine the 3 representations --------------------------
__global__ void k_combine(const float* __restrict__ w_comb,
                          const float* __restrict__ b_comb,
                          float* __restrict__ out){
    __shared__ float s_buf[32];
    __shared__ float s_p[3];
    int c = blockIdx.x, tid = threadIdx.x;
    float e0[3], e1[3], e2[3];
    float p0=0.f,p1=0.f,p2=0.f;
    #pragma unroll
    for(int j=0;j<3;j++){
        int h = tid + j*256;
        e0[j] = g_name_e[c*HH+h];
        e1[j] = g_mention_e[c*HH+h];
        e2[j] = g_utt_e[c*HH+h];
        float w = w_comb[h];
        p0 += e0[j]*w; p1 += e1[j]*w; p2 += e2[j]*w;
    }
    float s0 = blockSum(p0, s_buf);
    float s1 = blockSum(p1, s_buf);
    float s2 = blockSum(p2, s_buf);
    if(tid==0){
        float bb = b_comb[0];
        s0 += bb;
        s1 = (g_mcount[c]  > 0) ? (s1 + bb) : -INFINITY;
        s2 = (g_has_utt[c] > 0) ? (s2 + bb) : -INFINITY;
        float mx = fmaxf(s0, fmaxf(s1, s2));
        float q0 = __expf(s0-mx);
        float q1 = (s1 == -INFINITY) ? 0.f : __expf(s1-mx);
        float q2 = (s2 == -INFINITY) ? 0.f : __expf(s2-mx);
        float d = q0+q1+q2;
        s_p[0]=q0/d; s_p[1]=q1/d; s_p[2]=q2/d;
    }
    __syncthreads();
    #pragma unroll
    for(int j=0;j<3;j++){
        int h = tid + j*256;
        out[c*HH+h] = s_p[0]*e0[j] + s_p[1]*e1[j] + s_p[2]*e2[j];
    }
}

// ---------------- launch -----------------------------------------------------
extern "C" void kernel_launch(void* const* d_in, const int* in_sizes, int n_in,
                              void* d_out, int out_size){
    (void)in_sizes; (void)n_in; (void)out_size;
    const float* se          = (const float*)d_in[0];
    const float* nmask       = (const float*)d_in[1];
    const float* umask       = (const float*)d_in[2];
    const float* mmask       = (const float*)d_in[3];
    const int*   mids        = (const int*)  d_in[4];
    const float* w_name_tok  = (const float*)d_in[5];
    const float* b_name_tok  = (const float*)d_in[6];
    const float* w_name      = (const float*)d_in[7];
    const float* b_name      = (const float*)d_in[8];
    const float* w_men_tok   = (const float*)d_in[9];
    const float* b_men_tok   = (const float*)d_in[10];
    const float* w_men       = (const float*)d_in[11];
    const float* b_men       = (const float*)d_in[12];
    const float* w_utt       = (const float*)d_in[13];
    const float* b_utt       = (const float*)d_in[14];
    const float* w_comb      = (const float*)d_in[15];
    const float* b_comb      = (const float*)d_in[16];
    float* out = (float*)d_out;

    k_token    <<<TT/8,  256>>>(se, w_name_tok, b_name_tok, w_men_tok, b_men_tok, w_utt, b_utt);
    k_names    <<<CC*NB, 256>>>(se, nmask, w_name, b_name);
    k_name_e   <<<CC,    256>>>();
    k_mentions <<<MM,    256>>>(se, mmask, w_men, b_men);
    k_mention_e<<<CC,    256>>>(mids);
    k_utts     <<<CC,    256>>>(se, umask);
    k_combine  <<<CC,    256>>>(w_comb, b_comb, out);
}

// round 4
// speedup vs baseline: 1.4533x; 1.4533x over previous
#include <cuda_runtime.h>
#include <math.h>

#define NB 64
#define SS 512
#define HH 768
#define HV (HH/4)    // 192 float4 per row
#define CC 50
#define MM 2000
#define TT (NB*SS)   // 32768
#define UCH 8        // utterance chunks per character
#define UCHT (TT/UCH)// 4096 tokens per chunk

// ---------------- scratch (device globals; no allocations allowed) ----------
__device__ __align__(16) float g_nts[TT];
__device__ __align__(16) float g_mts[TT];
__device__ __align__(16) float g_uts[TT];
__device__ __align__(16) float g_names_emb[(size_t)CC*NB*HH];  // 9.8 MB
__device__ float g_nscore[CC*NB];
__device__ __align__(16) float g_name_e[CC*HH];
__device__ __align__(16) float g_memb[(size_t)MM*HH];          // 6 MB
__device__ float g_mscore[MM];
__device__ __align__(16) float g_mention_e[CC*HH];
__device__ int   g_mcount[CC];
__device__ __align__(16) float g_utt_V[(size_t)CC*UCH*HH];     // 1.2 MB
__device__ float g_utt_m[CC*UCH];
__device__ float g_utt_s[CC*UCH];
__device__ __align__(16) float g_utt_e[CC*HH];
__device__ int   g_has_utt[CC];

// ---------------- reductions -------------------------------------------------
__device__ __forceinline__ float warpSum(float v){
    #pragma unroll
    for(int o=16;o;o>>=1) v += __shfl_xor_sync(0xffffffffu, v, o);
    return v;
}
__device__ __forceinline__ float warpMax(float v){
    #pragma unroll
    for(int o=16;o;o>>=1) v = fmaxf(v, __shfl_xor_sync(0xffffffffu, v, o));
    return v;
}
template<int NW>
__device__ __forceinline__ float blockSumT(float v, float* buf){
    int lane = threadIdx.x & 31, wid = threadIdx.x >> 5;
    v = warpSum(v);
    if(lane == 0) buf[wid] = v;
    __syncthreads();
    if(wid == 0){
        float r = (lane < NW) ? buf[lane] : 0.f;
        r = warpSum(r);
        if(lane == 0) buf[0] = r;
    }
    __syncthreads();
    float r = buf[0];
    __syncthreads();
    return r;
}
template<int NW>
__device__ __forceinline__ float blockMaxT(float v, float* buf){
    int lane = threadIdx.x & 31, wid = threadIdx.x >> 5;
    v = warpMax(v);
    if(lane == 0) buf[wid] = v;
    __syncthreads();
    if(wid == 0){
        float r = (lane < NW) ? buf[lane] : -INFINITY;
        r = warpMax(r);
        if(lane == 0) buf[0] = r;
    }
    __syncthreads();
    float r = buf[0];
    __syncthreads();
    return r;
}

// ---------------- k1: per-token scalars nts/mts/uts --------------------------
// warp-per-token; 256 threads, vectorized LDG.128
__global__ void k_token(const float* __restrict__ se,
                        const float* __restrict__ wn, const float* __restrict__ bn,
                        const float* __restrict__ wm, const float* __restrict__ bm,
                        const float* __restrict__ wu, const float* __restrict__ bu){
    __shared__ float4 s_wn[HV], s_wm[HV], s_wu[HV];
    for(int i=threadIdx.x;i<HV;i+=256){
        s_wn[i]=((const float4*)wn)[i];
        s_wm[i]=((const float4*)wm)[i];
        s_wu[i]=((const float4*)wu)[i];
    }
    __syncthreads();
    int warp = threadIdx.x >> 5, lane = threadIdx.x & 31;
    int t = blockIdx.x*8 + warp;
    const float4* row = (const float4*)(se + (size_t)t*HH);
    float a=0.f, b=0.f, c=0.f;
    #pragma unroll
    for(int j=lane;j<HV;j+=32){
        float4 x = row[j];
        float4 n = s_wn[j], m = s_wm[j], u = s_wu[j];
        a = fmaf(x.x,n.x,fmaf(x.y,n.y,fmaf(x.z,n.z,fmaf(x.w,n.w,a))));
        b = fmaf(x.x,m.x,fmaf(x.y,m.y,fmaf(x.z,m.z,fmaf(x.w,m.w,b))));
        c = fmaf(x.x,u.x,fmaf(x.y,u.y,fmaf(x.z,u.z,fmaf(x.w,u.w,c))));
    }
    a = warpSum(a); b = warpSum(b); c = warpSum(c);
    if(lane == 0){
        g_nts[t] = a + bn[0];
        g_mts[t] = b + bm[0];
        g_uts[t] = c + bu[0];
    }
}

// ---------------- k2: names per (c,b): one CTA per (c,b), 192 threads --------
__global__ void k_names(const float* __restrict__ se,
                        const float* __restrict__ nmask,
                        const float* __restrict__ w_name,
                        const float* __restrict__ b_name){
    __shared__ int   s_idx[SS];
    __shared__ float s_w[SS];
    __shared__ float s_buf[32];
    __shared__ int   s_cnt;
    int c = blockIdx.x / NB, b = blockIdx.x % NB, tid = threadIdx.x;
    if(tid==0) s_cnt = 0;
    __syncthreads();
    const float* mrow = nmask + c*SS;
    const float* ntsr = g_nts + b*SS;
    float lm = -INFINITY;
    for(int s=tid;s<SS;s+=192){
        if(mrow[s]==0.0f){
            int p = atomicAdd(&s_cnt,1);
            if(p < SS) s_idx[p] = s;
            lm = fmaxf(lm, ntsr[s]);
        }
    }
    float mx = blockMaxT<6>(lm, s_buf);
    int cnt = min(s_cnt, SS);
    float ls = 0.f;
    for(int i=tid;i<cnt;i+=192){
        float e = __expf(ntsr[s_idx[i]] - mx);
        s_w[i] = e; ls += e;
    }
    float den = blockSumT<6>(ls, s_buf);
    float inv = 1.0f/den;
    const float4* base4 = (const float4*)se + (size_t)b*SS*HV;
    float4 a = make_float4(0.f,0.f,0.f,0.f);
    int i=0;
    for(; i+4<=cnt; i+=4){
        float w0=s_w[i], w1=s_w[i+1], w2=s_w[i+2], w3=s_w[i+3];
        float4 x0 = base4[(size_t)s_idx[i]  *HV + tid];
        float4 x1 = base4[(size_t)s_idx[i+1]*HV + tid];
        float4 x2 = base4[(size_t)s_idx[i+2]*HV + tid];
        float4 x3 = base4[(size_t)s_idx[i+3]*HV + tid];
        a.x = fmaf(w0,x0.x,fmaf(w1,x1.x,fmaf(w2,x2.x,fmaf(w3,x3.x,a.x))));
        a.y = fmaf(w0,x0.y,fmaf(w1,x1.y,fmaf(w2,x2.y,fmaf(w3,x3.y,a.y))));
        a.z = fmaf(w0,x0.z,fmaf(w1,x1.z,fmaf(w2,x2.z,fmaf(w3,x3.z,a.z))));
        a.w = fmaf(w0,x0.w,fmaf(w1,x1.w,fmaf(w2,x2.w,fmaf(w3,x3.w,a.w))));
    }
    for(; i<cnt; i++){
        float w = s_w[i];
        float4 x = base4[(size_t)s_idx[i]*HV + tid];
        a.x = fmaf(w,x.x,a.x); a.y = fmaf(w,x.y,a.y);
        a.z = fmaf(w,x.z,a.z); a.w = fmaf(w,x.w,a.w);
    }
    a.x*=inv; a.y*=inv; a.z*=inv; a.w*=inv;
    ((float4*)g_names_emb)[((size_t)c*NB + b)*HV + tid] = a;
    float4 wv = ((const float4*)w_name)[tid];
    float part = a.x*wv.x + a.y*wv.y + a.z*wv.z + a.w*wv.w;
    float sc = blockSumT<6>(part, s_buf);
    if(tid==0) g_nscore[c*NB + b] = sc + b_name[0];
}

// ---------------- k3: softmax over blocks -> name_e (192 threads) ------------
__global__ void k_name_e(){
    __shared__ float s_p[NB];
    __shared__ float s_buf[32];
    int c = blockIdx.x, tid = threadIdx.x;
    float v = (tid < NB) ? g_nscore[c*NB + tid] : -INFINITY;
    float mx = blockMaxT<6>(v, s_buf);
    float e = (tid < NB) ? __expf(v - mx) : 0.f;
    float den = blockSumT<6>(e, s_buf);
    if(tid < NB) s_p[tid] = e/den;
    __syncthreads();
    const float4* emb4 = (const float4*)g_names_emb + (size_t)c*NB*HV;
    float4 a = make_float4(0.f,0.f,0.f,0.f);
    #pragma unroll 4
    for(int b=0;b<NB;b++){
        float p = s_p[b];
        float4 x = emb4[(size_t)b*HV + tid];
        a.x = fmaf(p,x.x,a.x); a.y = fmaf(p,x.y,a.y);
        a.z = fmaf(p,x.z,a.z); a.w = fmaf(p,x.w,a.w);
    }
    ((float4*)g_name_e)[c*HV + tid] = a;
}

// ---------------- k4: mentions — sparse masked attention (192 threads) -------
#define MCAP 2048
__global__ void k_mentions(const float* __restrict__ se,
                           const float* __restrict__ mmask,
                           const float* __restrict__ w_men,
                           const float* __restrict__ b_men){
    __shared__ int   s_idx[MCAP];
    __shared__ float s_w[MCAP];
    __shared__ float s_buf[32];
    __shared__ int   s_cnt;
    int m = blockIdx.x, tid = threadIdx.x;
    if(tid==0) s_cnt = 0;
    __syncthreads();
    const float4* row4 = (const float4*)(mmask + (size_t)m*TT);
    for(int i=tid;i<TT/4;i+=192){
        float4 v = __ldcs(row4 + i);     // streaming: don't evict se from L2
        int t = i*4;
        if(v.x==0.f){ int p=atomicAdd(&s_cnt,1); if(p<MCAP) s_idx[p]=t;   }
        if(v.y==0.f){ int p=atomicAdd(&s_cnt,1); if(p<MCAP) s_idx[p]=t+1; }
        if(v.z==0.f){ int p=atomicAdd(&s_cnt,1); if(p<MCAP) s_idx[p]=t+2; }
        if(v.w==0.f){ int p=atomicAdd(&s_cnt,1); if(p<MCAP) s_idx[p]=t+3; }
    }
    __syncthreads();
    int cnt = min(s_cnt, MCAP);
    float lm = -INFINITY;
    for(int i=tid;i<cnt;i+=192) lm = fmaxf(lm, g_mts[s_idx[i]]);
    float mx = blockMaxT<6>(lm, s_buf);
    float ls = 0.f;
    for(int i=tid;i<cnt;i+=192){
        float e = __expf(g_mts[s_idx[i]] - mx);
        s_w[i] = e; ls += e;
    }
    float den = blockSumT<6>(ls, s_buf);
    float inv = 1.f/den;
    const float4* se4 = (const float4*)se;
    float4 a = make_float4(0.f,0.f,0.f,0.f);
    int i=0;
    for(; i+4<=cnt; i+=4){
        float w0=s_w[i], w1=s_w[i+1], w2=s_w[i+2], w3=s_w[i+3];
        float4 x0 = __ldg(se4 + (size_t)s_idx[i]  *HV + tid);
        float4 x1 = __ldg(se4 + (size_t)s_idx[i+1]*HV + tid);
        float4 x2 = __ldg(se4 + (size_t)s_idx[i+2]*HV + tid);
        float4 x3 = __ldg(se4 + (size_t)s_idx[i+3]*HV + tid);
        a.x = fmaf(w0,x0.x,fmaf(w1,x1.x,fmaf(w2,x2.x,fmaf(w3,x3.x,a.x))));
        a.y = fmaf(w0,x0.y,fmaf(w1,x1.y,fmaf(w2,x2.y,fmaf(w3,x3.y,a.y))));
        a.z = fmaf(w0,x0.z,fmaf(w1,x1.z,fmaf(w2,x2.z,fmaf(w3,x3.z,a.z))));
        a.w = fmaf(w0,x0.w,fmaf(w1,x1.w,fmaf(w2,x2.w,fmaf(w3,x3.w,a.w))));
    }
    for(; i<cnt; i++){
        float w = s_w[i];
        float4 x = __ldg(se4 + (size_t)s_idx[i]*HV + tid);
        a.x = fmaf(w,x.x,a.x); a.y = fmaf(w,x.y,a.y);
        a.z = fmaf(w,x.z,a.z); a.w = fmaf(w,x.w,a.w);
    }
    a.x*=inv; a.y*=inv; a.z*=inv; a.w*=inv;
    ((float4*)g_memb)[(size_t)m*HV + tid] = a;
    float4 wv = ((const float4*)w_men)[tid];
    float part = a.x*wv.x + a.y*wv.y + a.z*wv.z + a.w*wv.w;
    float sc = blockSumT<6>(part, s_buf);
    if(tid==0) g_mscore[m] = sc + b_men[0];
}

// ---------------- k5: segment softmax over mentions -> mention_e -------------
#define SCAP 512
__global__ void k_mention_e(const int* __restrict__ ids){
    __shared__ int   s_idx[SCAP];
    __shared__ float s_w[SCAP];
    __shared__ float s_buf[32];
    __shared__ int   s_cnt;
    int c = blockIdx.x, tid = threadIdx.x;
    if(tid==0) s_cnt = 0;
    __syncthreads();
    for(int m=tid;m<MM;m+=192)
        if(ids[m]==c){ int p=atomicAdd(&s_cnt,1); if(p<SCAP) s_idx[p]=m; }
    __syncthreads();
    int cnt = min(s_cnt, SCAP);
    if(tid==0) g_mcount[c] = cnt;
    float lm = -INFINITY;
    for(int i=tid;i<cnt;i+=192) lm = fmaxf(lm, g_mscore[s_idx[i]]);
    float mx = blockMaxT<6>(lm, s_buf);
    float ls = 0.f;
    for(int i=tid;i<cnt;i+=192){
        float e = __expf(g_mscore[s_idx[i]] - mx);
        s_w[i] = e; ls += e;
    }
    float den = blockSumT<6>(ls, s_buf);
    float inv = cnt ? 1.f/den : 0.f;
    const float4* memb4 = (const float4*)g_memb;
    float4 a = make_float4(0.f,0.f,0.f,0.f);
    int i=0;
    for(; i+4<=cnt; i+=4){
        float w0=s_w[i]*inv, w1=s_w[i+1]*inv, w2=s_w[i+2]*inv, w3=s_w[i+3]*inv;
        float4 x0 = memb4[(size_t)s_idx[i]  *HV + tid];
        float4 x1 = memb4[(size_t)s_idx[i+1]*HV + tid];
        float4 x2 = memb4[(size_t)s_idx[i+2]*HV + tid];
        float4 x3 = memb4[(size_t)s_idx[i+3]*HV + tid];
        a.x = fmaf(w0,x0.x,fmaf(w1,x1.x,fmaf(w2,x2.x,fmaf(w3,x3.x,a.x))));
        a.y = fmaf(w0,x0.y,fmaf(w1,x1.y,fmaf(w2,x2.y,fmaf(w3,x3.y,a.y))));
        a.z = fmaf(w0,x0.z,fmaf(w1,x1.z,fmaf(w2,x2.z,fmaf(w3,x3.z,a.z))));
        a.w = fmaf(w0,x0.w,fmaf(w1,x1.w,fmaf(w2,x2.w,fmaf(w3,x3.w,a.w))));
    }
    for(; i<cnt; i++){
        float w = s_w[i]*inv;
        float4 x = memb4[(size_t)s_idx[i]*HV + tid];
        a.x = fmaf(w,x.x,a.x); a.y = fmaf(w,x.y,a.y);
        a.z = fmaf(w,x.z,a.z); a.w = fmaf(w,x.w,a.w);
    }
    ((float4*)g_mention_e)[c*HV + tid] = a;
}

// ---------------- k6a: utterances — chunked partial softmax ------------------
#define UCAP 1024
__global__ void k_utt_chunk(const float* __restrict__ se,
                            const float* __restrict__ umask){
    __shared__ int   s_idx[UCAP];
    __shared__ float s_w[UCAP];
    __shared__ float s_buf[32];
    __shared__ int   s_cnt;
    int c = blockIdx.x / UCH, ch = blockIdx.x % UCH, tid = threadIdx.x;
    if(tid==0) s_cnt = 0;
    __syncthreads();
    const float4* row4 = (const float4*)(umask + (size_t)c*TT + ch*UCHT);
    int tbase = ch*UCHT;
    for(int i=tid;i<UCHT/4;i+=192){
        float4 v = __ldcs(row4 + i);
        int t = tbase + i*4;
        if(v.x==0.f){ int p=atomicAdd(&s_cnt,1); if(p<UCAP) s_idx[p]=t;   }
        if(v.y==0.f){ int p=atomicAdd(&s_cnt,1); if(p<UCAP) s_idx[p]=t+1; }
        if(v.z==0.f){ int p=atomicAdd(&s_cnt,1); if(p<UCAP) s_idx[p]=t+2; }
        if(v.w==0.f){ int p=atomicAdd(&s_cnt,1); if(p<UCAP) s_idx[p]=t+3; }
    }
    __syncthreads();
    int cnt = min(s_cnt, UCAP);
    float lm = -INFINITY;
    for(int i=tid;i<cnt;i+=192) lm = fmaxf(lm, g_uts[s_idx[i]]);
    float mx = blockMaxT<6>(lm, s_buf);     // -inf if empty chunk
    float ls = 0.f;
    for(int i=tid;i<cnt;i+=192){
        float e = __expf(g_uts[s_idx[i]] - mx);
        s_w[i] = e; ls += e;
    }
    float den = blockSumT<6>(ls, s_buf);
    const float4* se4 = (const float4*)se;
    float4 a = make_float4(0.f,0.f,0.f,0.f);
    int i=0;
    for(; i+4<=cnt; i+=4){
        float w0=s_w[i], w1=s_w[i+1], w2=s_w[i+2], w3=s_w[i+3];
        float4 x0 = __ldg(se4 + (size_t)s_idx[i]  *HV + tid);
        float4 x1 = __ldg(se4 + (size_t)s_idx[i+1]*HV + tid);
        float4 x2 = __ldg(se4 + (size_t)s_idx[i+2]*HV + tid);
        float4 x3 = __ldg(se4 + (size_t)s_idx[i+3]*HV + tid);
        a.x = fmaf(w0,x0.x,fmaf(w1,x1.x,fmaf(w2,x2.x,fmaf(w3,x3.x,a.x))));
        a.y = fmaf(w0,x0.y,fmaf(w1,x1.y,fmaf(w2,x2.y,fmaf(w3,x3.y,a.y))));
        a.z = fmaf(w0,x0.z,fmaf(w1,x1.z,fmaf(w2,x2.z,fmaf(w3,x3.z,a.z))));
        a.w = fmaf(w0,x0.w,fmaf(w1,x1.w,fmaf(w2,x2.w,fmaf(w3,x3.w,a.w))));
    }
    for(; i<cnt; i++){
        float w = s_w[i];
        float4 x = __ldg(se4 + (size_t)s_idx[i]*HV + tid);
        a.x = fmaf(w,x.x,a.x); a.y = fmaf(w,x.y,a.y);
        a.z = fmaf(w,x.z,a.z); a.w = fmaf(w,x.w,a.w);
    }
    // store unnormalized partials
    ((float4*)g_utt_V)[((size_t)c*UCH + ch)*HV + tid] = a;
    if(tid==0){
        g_utt_m[c*UCH + ch] = mx;
        g_utt_s[c*UCH + ch] = den;   // 0 if empty
    }
}

// ---------------- k6b: combine utterance chunks ------------------------------
__global__ void k_utt_comb(){
    int c = blockIdx.x, tid = threadIdx.x;
    float M = -INFINITY;
    #pragma unroll
    for(int ch=0;ch<UCH;ch++) M = fmaxf(M, g_utt_m[c*UCH+ch]);
    if(M == -INFINITY){                 // no utterance tokens: zeros
        if(tid==0) g_has_utt[c] = 0;
        float4 z = make_float4(0.f,0.f,0.f,0.f);
        ((float4*)g_utt_e)[c*HV + tid] = z;
        return;
    }
    float den = 0.f;
    float f[UCH];
    #pragma unroll
    for(int ch=0;ch<UCH;ch++){
        float m = g_utt_m[c*UCH+ch];
        float e = (m == -INFINITY) ? 0.f : __expf(m - M);
        f[ch] = e;
        den += e * g_utt_s[c*UCH+ch];
    }
    float inv = 1.f/den;
    const float4* V4 = (const float4*)g_utt_V + (size_t)c*UCH*HV;
    float4 a = make_float4(0.f,0.f,0.f,0.f);
    #pragma unroll
    for(int ch=0;ch<UCH;ch++){
        float w = f[ch]*inv;
        float4 x = V4[(size_t)ch*HV + tid];
        a.x = fmaf(w,x.x,a.x); a.y = fmaf(w,x.y,a.y);
        a.z = fmaf(w,x.z,a.z); a.w = fmaf(w,x.w,a.w);
    }
    ((float4*)g_utt_e)[c*HV + tid] = a;
    if(tid==0) g_has_utt[c] = 1;
}

// ---------------- k7: combine the 3 representations (256 threads) ------------
__global__ void k_combine(const float* __restrict__ w_comb,
                          const float* __restrict__ b_comb,
                          float* __restrict__ out){
    __shared__ float s_buf[32];
    __shared__ float s_p[3];
    int c = blockIdx.x, tid = threadIdx.x;
    float e0[3], e1[3], e2[3];
    float p0=0.f,p1=0.f,p2=0.f;
    #pragma unroll
    for(int j=0;j<3;j++){
        int h = tid + j*256;
        e0[j] = g_name_e[c*HH+h];
        e1[j] = g_mention_e[c*HH+h];
        e2[j] = g_utt_e[c*HH+h];
        float w = w_comb[h];
        p0 += e0[j]*w; p1 += e1[j]*w; p2 += e2[j]*w;
    }
    float s0 = blockSumT<8>(p0, s_buf);
    float s1 = blockSumT<8>(p1, s_buf);
    float s2 = blockSumT<8>(p2, s_buf);
    if(tid==0){
        float bb = b_comb[0];
        s0 += bb;
        s1 = (g_mcount[c]  > 0) ? (s1 + bb) : -INFINITY;
        s2 = (g_has_utt[c] > 0) ? (s2 + bb) : -INFINITY;
        float mx = fmaxf(s0, fmaxf(s1, s2));
        float q0 = __expf(s0-mx);
        float q1 = (s1 == -INFINITY) ? 0.f : __expf(s1-mx);
        float q2 = (s2 == -INFINITY) ? 0.f : __expf(s2-mx);
        float d = q0+q1+q2;
        s_p[0]=q0/d; s_p[1]=q1/d; s_p[2]=q2/d;
    }
    __syncthreads();
    #pragma unroll
    for(int j=0;j<3;j++){
        int h = tid + j*256;
        out[c*HH+h] = s_p[0]*e0[j] + s_p[1]*e1[j] + s_p[2]*e2[j];
    }
}

// ---------------- launch -----------------------------------------------------
extern "C" void kernel_launch(void* const* d_in, const int* in_sizes, int n_in,
                              void* d_out, int out_size){
    (void)in_sizes; (void)n_in; (void)out_size;
    const float* se          = (const float*)d_in[0];
    const float* nmask       = (const float*)d_in[1];
    const float* umask       = (const float*)d_in[2];
    const float* mmask       = (const float*)d_in[3];
    const int*   mids        = (const int*)  d_in[4];
    const float* w_name_tok  = (const float*)d_in[5];
    const float* b_name_tok  = (const float*)d_in[6];
    const float* w_name      = (const float*)d_in[7];
    const float* b_name      = (const float*)d_in[8];
    const float* w_men_tok   = (const float*)d_in[9];
    const float* b_men_tok   = (const float*)d_in[10];
    const float* w_men       = (const float*)d_in[11];
    const float* b_men       = (const float*)d_in[12];
    const float* w_utt       = (const float*)d_in[13];
    const float* b_utt       = (const float*)d_in[14];
    const float* w_comb      = (const float*)d_in[15];
    const float* b_comb      = (const float*)d_in[16];
    float* out = (float*)d_out;

    k_token     <<<TT/8,   256>>>(se, w_name_tok, b_name_tok, w_men_tok, b_men_tok, w_utt, b_utt);
    k_mentions  <<<MM,     192>>>(se, mmask, w_men, b_men);
    k_names     <<<CC*NB,  192>>>(se, nmask, w_name, b_name);
    k_name_e    <<<CC,     192>>>();
    k_mention_e <<<CC,     192>>>(mids);
    k_utt_chunk <<<CC*UCH, 192>>>(se, umask);
    k_utt_comb  <<<CC,     192>>>();
    k_combine   <<<CC,     256>>>(w_comb, b_comb, out);
}